// round 16
// baseline (speedup 1.0000x reference)
#include <cuda_runtime.h>
#include <stdint.h>

// EmotionModel: out = r + clip(softmax(r * (e @ (W_Q^T W_K)))^3 * colsum(W_D) + sum(b_D), -1, 1)
// B = 1,048,576 rows, D = 7.
// R16: byte-identical resubmit of R15 (broker died pre-compile). Base = R13
// (18.7us, cp.async double-buffer, issue-bound 62%). Changes under test:
// M/col/sumb in REGISTERS across the 4-tile loop (deletes 49 LDS per row),
// softmax max-shift dropped (R14 validated numerics), plain launch_bounds.

#define THREADS 256
#define TILE_ROWS 256
#define D 7
#define TILE_FLOATS (TILE_ROWS * D)        // 1792 floats = 7168 B per buffer
#define NT4 (TILE_FLOATS / 4)              // 448 float4 per buffer per tile
#define GRID 1024

// smem float offsets: [E buf0][E buf1][R buf0][R buf1]
#define E_OFF(b) ((b) * TILE_FLOATS)
#define R_OFF(b) (2 * TILE_FLOATS + (b) * TILE_FLOATS)

__device__ __forceinline__ void cp16(uint32_t dst, const void* src) {
    asm volatile("cp.async.cg.shared.global [%0], [%1], 16;" :: "r"(dst), "l"(src));
}
__device__ __forceinline__ void cp4(uint32_t dst, const void* src) {
    asm volatile("cp.async.ca.shared.global [%0], [%1], 4;" :: "r"(dst), "l"(src));
}
#define CP_COMMIT()  asm volatile("cp.async.commit_group;")
#define CP_WAIT(N)   asm volatile("cp.async.wait_group %0;" :: "n"(N))

// e^x on the FMA pipe (no MUFU). Valid for |x| << 126 (here |x| = O(10)).
__device__ __forceinline__ float fexp(float x) {
    const float L2E = 1.442695041f;
    float z = fmaf(x, L2E, 12582912.0f);       // 1.5*2^23 magic round
    int   i = __float_as_int(z);
    float n = z - 12582912.0f;
    float f = fmaf(x, L2E, -n);                // f in [-0.5, 0.5]
    float p =             1.3333558146e-3f;
    p = fmaf(p, f,        9.6181291076e-3f);
    p = fmaf(p, f,        5.5504108664e-2f);
    p = fmaf(p, f,        2.4022650695e-1f);
    p = fmaf(p, f,        6.9314718056e-1f);
    p = fmaf(p, f,        1.0f);
    return __int_as_float(__float_as_int(p) + (i << 23));
}

template <bool VEC4>
__global__ __launch_bounds__(THREADS)
void emotion_kernel(const float* __restrict__ rep,
                    const float* __restrict__ emo,
                    const float* __restrict__ WQ,
                    const float* __restrict__ WK,
                    const float* __restrict__ WD,
                    const float* __restrict__ bD,
                    float* __restrict__ out,
                    int ntiles)
{
    __shared__ __align__(16) float dsm[4 * TILE_FLOATS];   // 28 KB, static
    __shared__ float sWQ[49];
    __shared__ float sWK[49];
    __shared__ float sM[49];       // M[k][i] = sum_j WQ[j][k] * WK[j][i]
    __shared__ float sCol[D];      // colsum(W_D)
    __shared__ float sSumB;        // sum(b_D)

    const int tid = threadIdx.x;
    const uint32_t dsm_base = (uint32_t)__cvta_generic_to_shared(dsm);

    // issue async load of a tile into buffer b
    auto issue_load = [&](int tile_, int b) {
        const size_t base = (size_t)tile_ * TILE_FLOATS;
        if (VEC4) {
            const float4* e4 = (const float4*)(emo + base);
            const float4* r4 = (const float4*)(rep + base);
            const uint32_t de = dsm_base + E_OFF(b) * 4;
            const uint32_t dr = dsm_base + R_OFF(b) * 4;
            for (int i = tid; i < NT4; i += THREADS) {
                cp16(de + i * 16, e4 + i);
                cp16(dr + i * 16, r4 + i);
            }
        } else {
            const float* ep = emo + base;
            const float* rp = rep + base;
            const uint32_t de = dsm_base + E_OFF(b) * 4;
            const uint32_t dr = dsm_base + R_OFF(b) * 4;
            for (int i = tid; i < TILE_FLOATS; i += THREADS) {
                cp4(de + i * 4, ep + i);
                cp4(dr + i * 4, rp + i);
            }
        }
    };

    // kick off tile 0 load before anything else (overlaps weight precompute)
    int tile = blockIdx.x;
    if (tile < ntiles) { issue_load(tile, 0); }
    CP_COMMIT();

    // ---- tiny per-block precompute --------------------------------------
    if (tid < 49) { sWQ[tid] = WQ[tid]; sWK[tid] = WK[tid]; }
    __syncthreads();
    if (tid < 49) {
        const int k = tid / 7, i = tid % 7;
        float acc = 0.f;
        #pragma unroll
        for (int j = 0; j < 7; j++) acc = fmaf(sWQ[j * 7 + k], sWK[j * 7 + i], acc);
        sM[tid] = acc;
    }
    if (tid >= 64 && tid < 64 + D) {
        const int i = tid - 64;
        float c = 0.f;
        #pragma unroll
        for (int j = 0; j < 7; j++) c += WD[j * 7 + i];
        sCol[i] = c;
    }
    if (tid == 96) {
        float s = 0.f;
        #pragma unroll
        for (int j = 0; j < 7; j++) s += bD[j];
        sSumB = s;
    }
    __syncthreads();

    // ---- weights into registers, once per CTA (amortized over 4 tiles) --
    float rM[49];
    #pragma unroll
    for (int i = 0; i < 49; i++) rM[i] = sM[i];
    float rCol[D];
    #pragma unroll
    for (int i = 0; i < D; i++) rCol[i] = sCol[i];
    const float sumb = sSumB;

    int p = 0;  // current buffer parity
    while (tile < ntiles) {
        const int next = tile + GRID;
        const bool has_next = next < ntiles;
        if (has_next) {
            issue_load(next, p ^ 1);
            CP_COMMIT();
            CP_WAIT(1);           // current tile's group complete
        } else {
            CP_WAIT(0);
        }
        __syncthreads();          // staged data visible to all

        float* bufE = dsm + E_OFF(p);
        float* bufR = dsm + R_OFF(p);

        // ---- per-row math: one row per thread (7*tid mod 32 conflict-free)
        {
            const int row = tid;
            float e[D], rv[D];
            #pragma unroll
            for (int i = 0; i < D; i++) { e[i] = bufE[row * D + i]; rv[i] = bufR[row * D + i]; }

            float raw[D];
            #pragma unroll
            for (int i = 0; i < D; i++) {
                float acc = 0.f;
                #pragma unroll
                for (int k = 0; k < D; k++) acc = fmaf(e[k], rM[k * 7 + i], acc);  // reg operands
                raw[i] = acc * rv[i];
            }

            // softmax over 7, no max-shift (shift-invariant; |raw| = O(10))
            float psum = 0.f;
            #pragma unroll
            for (int i = 0; i < D; i++) { raw[i] = fexp(raw[i]); psum += raw[i]; }
            const float inv = __fdividef(1.0f, psum);

            #pragma unroll
            for (int i = 0; i < D; i++) {
                const float s  = raw[i] * inv;
                const float s3 = s * s * s;
                const float d  = fminf(fmaxf(fmaf(s3, rCol[i], sumb), -1.0f), 1.0f);
                bufE[row * D + i] = rv[i] + d;   // overwrite E buffer with output
            }
        }
        __syncthreads();          // outputs complete in smem

        // ---- coalesced store of tile ------------------------------------
        const size_t base = (size_t)tile * TILE_FLOATS;
        if (VEC4) {
            float4* o4 = (float4*)(out + base);
            const float4* se4 = (const float4*)bufE;
            for (int i = tid; i < NT4; i += THREADS) o4[i] = se4[i];
        } else {
            float* op = out + base;
            for (int i = tid; i < TILE_FLOATS; i += THREADS) op[i] = bufE[i];
        }

        if (!has_next) break;
        __syncthreads();          // buffer p fully read before next reuse
        tile = next;
        p ^= 1;
    }
}

extern "C" void kernel_launch(void* const* d_in, const int* in_sizes, int n_in,
                              void* d_out, int out_size)
{
    const float* rep = (const float*)d_in[0];
    const float* emo = (const float*)d_in[1];
    const float* WQ  = (const float*)d_in[2];
    const float* WK  = (const float*)d_in[3];
    const float* WD  = (const float*)d_in[4];
    const float* bD  = (const float*)d_in[5];
    float* out = (float*)d_out;

    const int n_rows = in_sizes[0] / D;                        // 1,048,576
    const int ntiles = (n_rows + TILE_ROWS - 1) / TILE_ROWS;   // 4096 exact

    const bool aligned16 =
        ((((uintptr_t)rep) | ((uintptr_t)emo) | ((uintptr_t)out)) & 15u) == 0;

    if (aligned16)
        emotion_kernel<true><<<GRID, THREADS>>>(rep, emo, WQ, WK, WD, bD, out, ntiles);
    else
        emotion_kernel<false><<<GRID, THREADS>>>(rep, emo, WQ, WK, WD, bD, out, ntiles);
}

// round 17
// speedup vs baseline: 1.1960x; 1.1960x over previous
#include <cuda_runtime.h>
#include <stdint.h>

// EmotionModel: out = r + clip(softmax(r * (e @ (W_Q^T W_K)))^3 * colsum(W_D) + sum(b_D), -1, 1)
// B = 1,048,576 rows, D = 7.
// R17: base = R13 (18.7us). R16 showed weights-in-regs kills occupancy (92 regs
// -> 22.8% occ -> 21.1us). This round: zero-register instruction cuts.
//  (a) __expf (MUFU idle; warp-level math shows total MUFU ~1.4us chip-wide),
//  (b) no softmax max-shift (validated rel_err 2.4e-8 in R14/R16),
//  (c) M padded to stride-8 -> broadcast weight loads 49 LDS -> 21 vector LDS,
//      col -> 3 vector LDS. Pipeline/occupancy shape of R13 preserved.

#define THREADS 256
#define TILE_ROWS 256
#define D 7
#define TILE_FLOATS (TILE_ROWS * D)        // 1792 floats = 7168 B per buffer
#define NT4 (TILE_FLOATS / 4)              // 448 float4 per buffer per tile
#define GRID 1024

// smem float offsets: [E buf0][E buf1][R buf0][R buf1]
#define E_OFF(b) ((b) * TILE_FLOATS)
#define R_OFF(b) (2 * TILE_FLOATS + (b) * TILE_FLOATS)

__device__ __forceinline__ void cp16(uint32_t dst, const void* src) {
    asm volatile("cp.async.cg.shared.global [%0], [%1], 16;" :: "r"(dst), "l"(src));
}
__device__ __forceinline__ void cp4(uint32_t dst, const void* src) {
    asm volatile("cp.async.ca.shared.global [%0], [%1], 4;" :: "r"(dst), "l"(src));
}
#define CP_COMMIT()  asm volatile("cp.async.commit_group;")
#define CP_WAIT(N)   asm volatile("cp.async.wait_group %0;" :: "n"(N))

template <bool VEC4>
__global__ __launch_bounds__(THREADS)
void emotion_kernel(const float* __restrict__ rep,
                    const float* __restrict__ emo,
                    const float* __restrict__ WQ,
                    const float* __restrict__ WK,
                    const float* __restrict__ WD,
                    const float* __restrict__ bD,
                    float* __restrict__ out,
                    int ntiles)
{
    __shared__ __align__(16) float dsm[4 * TILE_FLOATS];   // 28 KB, static
    __shared__ float sWQ[49];
    __shared__ float sWK[49];
    __shared__ __align__(16) float sMp[56];    // M padded: M[k][i] at sMp[8k+i]
    __shared__ __align__(16) float sColp[8];   // colsum(W_D), padded
    __shared__ float sSumB;                    // sum(b_D)

    const int tid = threadIdx.x;
    const uint32_t dsm_base = (uint32_t)__cvta_generic_to_shared(dsm);

    // issue async load of a tile into buffer b
    auto issue_load = [&](int tile_, int b) {
        const size_t base = (size_t)tile_ * TILE_FLOATS;
        if (VEC4) {
            const float4* e4 = (const float4*)(emo + base);
            const float4* r4 = (const float4*)(rep + base);
            const uint32_t de = dsm_base + E_OFF(b) * 4;
            const uint32_t dr = dsm_base + R_OFF(b) * 4;
            for (int i = tid; i < NT4; i += THREADS) {
                cp16(de + i * 16, e4 + i);
                cp16(dr + i * 16, r4 + i);
            }
        } else {
            const float* ep = emo + base;
            const float* rp = rep + base;
            const uint32_t de = dsm_base + E_OFF(b) * 4;
            const uint32_t dr = dsm_base + R_OFF(b) * 4;
            for (int i = tid; i < TILE_FLOATS; i += THREADS) {
                cp4(de + i * 4, ep + i);
                cp4(dr + i * 4, rp + i);
            }
        }
    };

    // kick off tile 0 load first (overlaps the weight precompute)
    int tile = blockIdx.x;
    if (tile < ntiles) { issue_load(tile, 0); }
    CP_COMMIT();

    // ---- tiny per-block precompute --------------------------------------
    if (tid < 49) { sWQ[tid] = WQ[tid]; sWK[tid] = WK[tid]; }
    __syncthreads();
    if (tid < 49) {
        const int k = tid / 7, i = tid % 7;
        float acc = 0.f;
        #pragma unroll
        for (int j = 0; j < 7; j++) acc = fmaf(sWQ[j * 7 + k], sWK[j * 7 + i], acc);
        sMp[k * 8 + i] = acc;                 // padded stride 8
    }
    if (tid >= 56 && tid < 56 + D) {
        const int i = tid - 56;
        float c = 0.f;
        #pragma unroll
        for (int j = 0; j < 7; j++) c += WD[j * 7 + i];
        sColp[i] = c;
    }
    if (tid == 96) {
        float s = 0.f;
        #pragma unroll
        for (int j = 0; j < 7; j++) s += bD[j];
        sSumB = s;
        sColp[7] = 0.f;
    }
    __syncthreads();

    const float sumb = sSumB;

    int p = 0;  // current buffer parity
    while (tile < ntiles) {
        const int next = tile + GRID;
        const bool has_next = next < ntiles;
        if (has_next) {
            issue_load(next, p ^ 1);
            CP_COMMIT();
            CP_WAIT(1);           // current tile's group complete
        } else {
            CP_WAIT(0);
        }
        __syncthreads();          // staged data visible to all

        float* bufE = dsm + E_OFF(p);
        float* bufR = dsm + R_OFF(p);

        // ---- per-row math: one row per thread (7*tid mod 32 conflict-free)
        {
            const int row = tid;
            float e[D], rv[D];
            #pragma unroll
            for (int i = 0; i < D; i++) { e[i] = bufE[row * D + i]; rv[i] = bufR[row * D + i]; }

            // raw = (e @ M) .* rv, M rows loaded as 128+64+32-bit broadcasts
            float raw[D];
            #pragma unroll
            for (int i = 0; i < D; i++) raw[i] = 0.f;
            #pragma unroll
            for (int k = 0; k < D; k++) {
                const float  ek = e[k];
                const float4 m0 = *(const float4*)&sMp[8 * k];
                const float2 m1 = *(const float2*)&sMp[8 * k + 4];
                const float  m2 = sMp[8 * k + 6];
                raw[0] = fmaf(ek, m0.x, raw[0]);
                raw[1] = fmaf(ek, m0.y, raw[1]);
                raw[2] = fmaf(ek, m0.z, raw[2]);
                raw[3] = fmaf(ek, m0.w, raw[3]);
                raw[4] = fmaf(ek, m1.x, raw[4]);
                raw[5] = fmaf(ek, m1.y, raw[5]);
                raw[6] = fmaf(ek, m2,   raw[6]);
            }
            #pragma unroll
            for (int i = 0; i < D; i++) raw[i] *= rv[i];

            // softmax over 7, no max-shift (shift-invariant; |raw| = O(10))
            float psum = 0.f;
            #pragma unroll
            for (int i = 0; i < D; i++) { raw[i] = __expf(raw[i]); psum += raw[i]; }
            const float inv = __fdividef(1.0f, psum);

            const float4 c0 = *(const float4*)&sColp[0];
            const float2 c1 = *(const float2*)&sColp[4];
            const float  c2 = sColp[6];
            const float col[D] = {c0.x, c0.y, c0.z, c0.w, c1.x, c1.y, c2};

            #pragma unroll
            for (int i = 0; i < D; i++) {
                const float s  = raw[i] * inv;
                const float s3 = s * s * s;
                const float d  = fminf(fmaxf(fmaf(s3, col[i], sumb), -1.0f), 1.0f);
                bufE[row * D + i] = rv[i] + d;   // overwrite E buffer with output
            }
        }
        __syncthreads();          // outputs complete in smem

        // ---- coalesced store of tile ------------------------------------
        const size_t base = (size_t)tile * TILE_FLOATS;
        if (VEC4) {
            float4* o4 = (float4*)(out + base);
            const float4* se4 = (const float4*)bufE;
            for (int i = tid; i < NT4; i += THREADS) o4[i] = se4[i];
        } else {
            float* op = out + base;
            for (int i = tid; i < TILE_FLOATS; i += THREADS) op[i] = bufE[i];
        }

        if (!has_next) break;
        __syncthreads();          // buffer p fully read before next reuse
        tile = next;
        p ^= 1;
    }
}

extern "C" void kernel_launch(void* const* d_in, const int* in_sizes, int n_in,
                              void* d_out, int out_size)
{
    const float* rep = (const float*)d_in[0];
    const float* emo = (const float*)d_in[1];
    const float* WQ  = (const float*)d_in[2];
    const float* WK  = (const float*)d_in[3];
    const float* WD  = (const float*)d_in[4];
    const float* bD  = (const float*)d_in[5];
    float* out = (float*)d_out;

    const int n_rows = in_sizes[0] / D;                        // 1,048,576
    const int ntiles = (n_rows + TILE_ROWS - 1) / TILE_ROWS;   // 4096 exact

    const bool aligned16 =
        ((((uintptr_t)rep) | ((uintptr_t)emo) | ((uintptr_t)out)) & 15u) == 0;

    if (aligned16)
        emotion_kernel<true><<<GRID, THREADS>>>(rep, emo, WQ, WK, WD, bD, out, ntiles);
    else
        emotion_kernel<false><<<GRID, THREADS>>>(rep, emo, WQ, WK, WD, bD, out, ntiles);
}